// round 1
// baseline (speedup 1.0000x reference)
#include <cuda_runtime.h>
#include <math.h>

// Problem dims
#define Bn 8
#define Tn 96
#define Sn 192
#define Dn 512
#define BT (Bn*Tn)   // 768

// Scratch (device globals: no allocation allowed)
__device__ float g_wq[BT * Dn];        // [B,T,D]   inputs @ Wq^T
__device__ float g_uh[Bn * Sn * Dn];   // [B,S,D]   mems @ Wc^T + bc
__device__ float g_p [BT * Sn];        // [B,T,S]   softmax probs
__device__ float g_c [BT * Dn];        // [B,T,D]   context

__device__ __forceinline__ float fast_tanh(float x) {
    // tanh(x) = 1 - 2/(exp(2x)+1); __expf/__fdividef => 2 MUFU, ~1e-6 accuracy
    float e = __expf(2.0f * x);
    return 1.0f - __fdividef(2.0f, e + 1.0f);
}

// ----------------------------------------------------------------------------
// Dual-input SGEMM: C[M,N] = [A1|A2] @ W^T (+bias)
// A1: [M,K1], A2: [M,K2] (may be null, K2=0), W: [N, K1+K2] row-major.
// Block tile 64x64, K-step 16, 256 threads, 4x4 microtile.
// Requires M%64==0, N%64==0, (K1+K2)%16==0, K1%16==0. All true here.
// ----------------------------------------------------------------------------
__global__ void __launch_bounds__(256) sgemm_dual(
    const float* __restrict__ A1, int K1,
    const float* __restrict__ A2, int K2,
    const float* __restrict__ W,
    const float* __restrict__ bias,
    float* __restrict__ C, int N)
{
    const int K = K1 + K2;
    __shared__ __align__(16) float As[16][68];
    __shared__ __align__(16) float Ws[16][68];

    const int tid  = threadIdx.x;
    const int tm   = tid >> 4;          // 0..15
    const int tn   = tid & 15;          // 0..15
    const int row0 = blockIdx.y * 64;
    const int col0 = blockIdx.x * 64;
    const int lrow = tid >> 2;          // 0..63
    const int lk4  = (tid & 3) << 2;    // 0,4,8,12

    float acc[4][4] = {};

    for (int k0 = 0; k0 < K; k0 += 16) {
        const int kk = k0 + lk4;
        float4 av, wv;
        if (kk < K1) av = *(const float4*)(A1 + (size_t)(row0 + lrow) * K1 + kk);
        else         av = *(const float4*)(A2 + (size_t)(row0 + lrow) * K2 + (kk - K1));
        wv = *(const float4*)(W + (size_t)(col0 + lrow) * K + kk);

        As[lk4 + 0][lrow] = av.x; As[lk4 + 1][lrow] = av.y;
        As[lk4 + 2][lrow] = av.z; As[lk4 + 3][lrow] = av.w;
        Ws[lk4 + 0][lrow] = wv.x; Ws[lk4 + 1][lrow] = wv.y;
        Ws[lk4 + 2][lrow] = wv.z; Ws[lk4 + 3][lrow] = wv.w;
        __syncthreads();

        #pragma unroll
        for (int k = 0; k < 16; k++) {
            float4 a = *(const float4*)&As[k][tm * 4];
            float4 b = *(const float4*)&Ws[k][tn * 4];
            float aa[4] = {a.x, a.y, a.z, a.w};
            float bb[4] = {b.x, b.y, b.z, b.w};
            #pragma unroll
            for (int i = 0; i < 4; i++)
                #pragma unroll
                for (int j = 0; j < 4; j++)
                    acc[i][j] += aa[i] * bb[j];
        }
        __syncthreads();
    }

    #pragma unroll
    for (int i = 0; i < 4; i++) {
        const int r = row0 + tm * 4 + i;
        const int c = col0 + tn * 4;
        float b0 = 0.f, b1 = 0.f, b2 = 0.f, b3 = 0.f;
        if (bias) { b0 = bias[c]; b1 = bias[c + 1]; b2 = bias[c + 2]; b3 = bias[c + 3]; }
        float4 o;
        o.x = acc[i][0] + b0; o.y = acc[i][1] + b1;
        o.z = acc[i][2] + b2; o.w = acc[i][3] + b3;
        *(float4*)(C + (size_t)r * N + c) = o;
    }
}

// ----------------------------------------------------------------------------
// Score + mask + softmax. One CTA per (b,t); thread s computes
// align[b,t,s] = sum_m tanh(wq[b,t,m] + uh[b,s,m]) * v[m], then block softmax.
// ----------------------------------------------------------------------------
__global__ void __launch_bounds__(256) score_softmax(
    const float* __restrict__ wq, const float* __restrict__ uh,
    const int* __restrict__ lens, const float* __restrict__ v,
    float* __restrict__ P, float* __restrict__ out_align, int write_align)
{
    const int t = blockIdx.x, b = blockIdx.y;
    const int tid = threadIdx.x;
    __shared__ __align__(16) float wq_sh[Dn];
    __shared__ __align__(16) float v_sh[Dn];
    __shared__ float red[256];

    for (int i = tid; i < Dn; i += 256) {
        wq_sh[i] = wq[((size_t)(b * Tn + t)) * Dn + i];
        v_sh[i]  = v[i];
    }
    __syncthreads();

    const int s = tid;
    const bool inrange = (s < Sn);
    const bool active  = inrange && (s < lens[b]);
    float val = -INFINITY;

    if (inrange) {
        const float4* u4  = (const float4*)(uh + ((size_t)(b * Sn + s)) * Dn);
        const float4* w4  = (const float4*)wq_sh;
        const float4* vv4 = (const float4*)v_sh;
        float acc = 0.f;
        #pragma unroll 4
        for (int j = 0; j < Dn / 4; j++) {
            float4 u = u4[j], w = w4[j], vv = vv4[j];
            acc += fast_tanh(w.x + u.x) * vv.x;
            acc += fast_tanh(w.y + u.y) * vv.y;
            acc += fast_tanh(w.z + u.z) * vv.z;
            acc += fast_tanh(w.w + u.w) * vv.w;
        }
        if (active) val = acc;
    }

    // block max
    red[tid] = val; __syncthreads();
    #pragma unroll
    for (int st = 128; st > 0; st >>= 1) {
        if (tid < st) red[tid] = fmaxf(red[tid], red[tid + st]);
        __syncthreads();
    }
    const float mx = red[0];
    __syncthreads();

    const float e = active ? __expf(val - mx) : 0.f;
    red[tid] = e; __syncthreads();
    #pragma unroll
    for (int st = 128; st > 0; st >>= 1) {
        if (tid < st) red[tid] += red[tid + st];
        __syncthreads();
    }
    const float inv = __fdividef(1.f, red[0]);

    if (inrange) {
        const float p = e * inv;
        const size_t o = ((size_t)(b * Tn + t)) * Sn + s;
        P[o] = p;
        if (write_align) out_align[o] = p;
    }
}

// ----------------------------------------------------------------------------
// Context: c[b,t,:] = sum_s P[b,t,s] * mems[b,s,:].
// One CTA per 4 consecutive t (same b since T%4==0); 128 threads * float4 = 512 d.
// ----------------------------------------------------------------------------
__global__ void __launch_bounds__(128) context_kernel(
    const float* __restrict__ P, const float* __restrict__ mems,
    float* __restrict__ C)
{
    const int bt0 = blockIdx.x * 4;
    const int b = bt0 / Tn;
    const int tid = threadIdx.x;
    __shared__ float p_sh[4][Sn];
    for (int i = tid; i < 4 * Sn; i += 128)
        p_sh[i / Sn][i % Sn] = P[(size_t)bt0 * Sn + i];
    __syncthreads();

    const float4* m4 = (const float4*)(mems + (size_t)b * Sn * Dn);
    float4 acc[4];
    #pragma unroll
    for (int i = 0; i < 4; i++) acc[i] = make_float4(0.f, 0.f, 0.f, 0.f);

    #pragma unroll 2
    for (int s = 0; s < Sn; s++) {
        float4 mv = m4[(size_t)s * (Dn / 4) + tid];
        #pragma unroll
        for (int i = 0; i < 4; i++) {
            float p = p_sh[i][s];
            acc[i].x += p * mv.x; acc[i].y += p * mv.y;
            acc[i].z += p * mv.z; acc[i].w += p * mv.w;
        }
    }
    #pragma unroll
    for (int i = 0; i < 4; i++)
        *(float4*)(C + (size_t)(bt0 + i) * Dn + tid * 4) = acc[i];
}

// ----------------------------------------------------------------------------
extern "C" void kernel_launch(void* const* d_in, const int* in_sizes, int n_in,
                              void* d_out, int out_size)
{
    const float* inputs = (const float*)d_in[0];  // [B,T,512]
    const float* mems   = (const float*)d_in[1];  // [B,S,512]
    const int*   lens   = (const int*)  d_in[2];  // [B]
    const float* Wq     = (const float*)d_in[3];  // [512,512]
    const float* Wc     = (const float*)d_in[4];  // [512,512]
    const float* bc     = (const float*)d_in[5];  // [512]
    const float* v      = (const float*)d_in[6];  // [512]
    const float* Wout   = (const float*)d_in[7];  // [512,1024]
    const float* bout   = (const float*)d_in[8];  // [512]
    float* out = (float*)d_out;

    float *wqb, *uhb, *pb, *cb;
    cudaGetSymbolAddress((void**)&wqb, g_wq);
    cudaGetSymbolAddress((void**)&uhb, g_uh);
    cudaGetSymbolAddress((void**)&pb,  g_p);
    cudaGetSymbolAddress((void**)&cb,  g_c);

    const int attn_elems  = BT * Dn;            // 393216
    const int align_elems = BT * Sn;            // 147456
    const int write_align = (out_size >= attn_elems + align_elems) ? 1 : 0;
    float* out_align = out + attn_elems;

    // 1) wq = inputs @ Wq^T         [768,512]
    sgemm_dual<<<dim3(Dn / 64, BT / 64), 256>>>(
        inputs, Dn, nullptr, 0, Wq, nullptr, wqb, Dn);

    // 2) uh = mems @ Wc^T + bc      [1536,512]
    sgemm_dual<<<dim3(Dn / 64, (Bn * Sn) / 64), 256>>>(
        mems, Dn, nullptr, 0, Wc, bc, uhb, Dn);

    // 3) scores + mask + softmax    [B,T,S]
    score_softmax<<<dim3(Tn, Bn), 256>>>(wqb, uhb, lens, v, pb, out_align, write_align);

    // 4) context c = P @ mems       [768,512]
    context_kernel<<<BT / 4, 128>>>(pb, mems, cb);

    // 5) attn_h = [c | inputs] @ Wout^T + bout   [768,512]
    sgemm_dual<<<dim3(Dn / 64, BT / 64), 256>>>(
        cb, Dn, inputs, Dn, Wout, bout, out, Dn);
}